// round 13
// baseline (speedup 1.0000x reference)
#include <cuda_runtime.h>
#include <math.h>

#define G     1024
#define GM    (G - 1)
#define NA    262144
#define NC    8
#define DT_F  0.1f
#define DEC_F 0.99f
#define SANG  0.6f
#define SLEN  3.0f

// Scratch (static device globals; no allocation anywhere)
__device__ float g_box[G * G * NC];       // 3x3 box sum, transposed (G,G,C) 32 MB
__device__ float g_dpher[NA * NC];        // per-agent pheromone delta        8 MB
__device__ int   g_winner[G * G];         // last-writer agent index + 1     4 MB (zero-init)

__device__ __forceinline__ float tanh_ap(float x) {
    float y; asm("tanh.approx.f32 %0, %1;" : "=f"(y) : "f"(x)); return y;
}

// ---------------------------------------------------------------------------
// Pass 1 (single): wrapped 3x3 box sum, (C,G,G) -> (G,G,C), channel-parallel.
// Thread = one (c,x) row, 4 y-cells (hsum geometry). Reads 3 wrapped rows
// (float4 + 2 edge scalars each); L2 serves the x±1 re-reads. Output scalars
// land in L2-resident g_box where partial sectors merge across channels.
// ---------------------------------------------------------------------------
__global__ void k_box3(const float* __restrict__ lat) {
    int t   = blockIdx.x * blockDim.x + threadIdx.x;   // C*G*G/4 threads
    int y0  = (t & 255) << 2;
    int row = t >> 8;                                  // c*G + x
    int c   = row >> 10;
    int x   = row & GM;
    int xm  = (x + GM) & GM;
    int xp  = (x + 1) & GM;
    int ylo = (y0 + GM) & GM;
    int yhi = (y0 + 4) & GM;

    const float* base = lat + ((size_t)c << 20);
    float cs[6] = {0, 0, 0, 0, 0, 0};
    const int rows[3] = {xm, x, xp};
#pragma unroll
    for (int r = 0; r < 3; r++) {
        const float* rp = base + ((size_t)rows[r] << 10);
        float4 m = __ldg((const float4*)(rp + y0));
        cs[0] += __ldg(rp + ylo);
        cs[1] += m.x; cs[2] += m.y; cs[3] += m.z; cs[4] += m.w;
        cs[5] += __ldg(rp + yhi);
    }
    float* dst = g_box + ((size_t)(x * G + y0)) * NC + c;
#pragma unroll
    for (int u = 0; u < 4; u++)
        dst[u * NC] = cs[u] + cs[u + 1] + cs[u + 2];
}

// ---------------------------------------------------------------------------
// Pass 2: per-agent sense + MLP + outputs. (R6 verbatim — best measured)
// ---------------------------------------------------------------------------
__device__ __forceinline__ void sense24(float px, float py, float vx, float vy,
                                        float* __restrict__ x) {
    const float CA = 0.8253356149096783f;   // cos(0.6)
    const float SA = 0.5646424733950354f;   // sin(0.6)
    float rinv = rsqrtf(vx * vx + vy * vy);
    float c0 = vx * rinv, s0 = vy * rinv;
    float cd[3], sd[3];
    cd[0] = c0;                 sd[0] = s0;
    cd[1] = c0 * CA - s0 * SA;  sd[1] = s0 * CA + c0 * SA;
    cd[2] = c0 * CA + s0 * SA;  sd[2] = s0 * CA - c0 * SA;
#pragma unroll
    for (int s = 0; s < 3; s++) {
        int ix = ((int)rintf(px + SLEN * cd[s])) & GM;
        int iy = ((int)rintf(py + SLEN * sd[s])) & GM;
        const float4* bp = (const float4*)(g_box + ((size_t)(ix * G + iy)) * NC);
        float4 u = bp[0], v = bp[1];
        x[s * 8 + 0] = u.x; x[s * 8 + 1] = u.y; x[s * 8 + 2] = u.z; x[s * 8 + 3] = u.w;
        x[s * 8 + 4] = v.x; x[s * 8 + 5] = v.y; x[s * 8 + 6] = v.z; x[s * 8 + 7] = v.w;
    }
}

__global__ __launch_bounds__(256) void k_agent(
    const float* __restrict__ pos, const float* __restrict__ vel,
    const float* __restrict__ W1,  const float* __restrict__ b1,
    const float* __restrict__ W2,  const float* __restrict__ b2,
    float* __restrict__ out)
{
    __shared__ __align__(16) float sW1[24 * 64];
    __shared__ __align__(16) float sB1[64];
    __shared__ __align__(16) float sW2[64 * 12];   // rows of 10 padded to 12
    __shared__ __align__(16) float sB2[12];

    int tid = threadIdx.x;
    for (int i = tid; i < 24 * 64; i += 256) sW1[i] = __ldg(W1 + i);
    if (tid < 64) sB1[tid] = __ldg(b1 + tid);
    for (int i = tid; i < 64 * 12; i += 256) {
        int k = i / 12, m = i - k * 12;
        sW2[i] = (m < 10) ? __ldg(W2 + k * 10 + m) : 0.0f;
    }
    if (tid < 12) sB2[tid] = (tid < 10) ? __ldg(b2 + tid) : 0.0f;
    __syncthreads();

    int aA = blockIdx.x * 512 + tid;     // two agents per thread
    int aB = aA + 256;

    float pxA = pos[aA], pyA = pos[NA + aA];
    float vxA = vel[aA], vyA = vel[NA + aA];
    float pxB = pos[aB], pyB = pos[NA + aB];
    float vxB = vel[aB], vyB = vel[NA + aB];

    float xA[24], xB[24];
    sense24(pxA, pyA, vxA, vyA, xA);
    sense24(pxB, pyB, vxB, vyB, xB);

    float ocA[10], ocB[10];
#pragma unroll
    for (int m = 0; m < 10; m++) { ocA[m] = sB2[m]; ocB[m] = sB2[m]; }

#pragma unroll
    for (int jq = 0; jq < 16; jq++) {
        float4 b4 = *(const float4*)&sB1[jq * 4];
        float4 aAcc = b4, bAcc = b4;
#pragma unroll
        for (int k = 0; k < 24; k++) {
            float4 w = *(const float4*)&sW1[k * 64 + jq * 4];
            aAcc.x = fmaf(xA[k], w.x, aAcc.x); aAcc.y = fmaf(xA[k], w.y, aAcc.y);
            aAcc.z = fmaf(xA[k], w.z, aAcc.z); aAcc.w = fmaf(xA[k], w.w, aAcc.w);
            bAcc.x = fmaf(xB[k], w.x, bAcc.x); bAcc.y = fmaf(xB[k], w.y, bAcc.y);
            bAcc.z = fmaf(xB[k], w.z, bAcc.z); bAcc.w = fmaf(xB[k], w.w, bAcc.w);
        }
        float hA[4], hB[4];
        hA[0] = tanh_ap(aAcc.x); hA[1] = tanh_ap(aAcc.y);
        hA[2] = tanh_ap(aAcc.z); hA[3] = tanh_ap(aAcc.w);
        hB[0] = tanh_ap(bAcc.x); hB[1] = tanh_ap(bAcc.y);
        hB[2] = tanh_ap(bAcc.z); hB[3] = tanh_ap(bAcc.w);
#pragma unroll
        for (int u = 0; u < 4; u++) {
            int j = jq * 4 + u;
            const float4* wr = (const float4*)&sW2[j * 12];
            float4 w0 = wr[0], w1 = wr[1], w2 = wr[2];
            float ha = hA[u], hb = hB[u];
            ocA[0] = fmaf(ha, w0.x, ocA[0]); ocB[0] = fmaf(hb, w0.x, ocB[0]);
            ocA[1] = fmaf(ha, w0.y, ocA[1]); ocB[1] = fmaf(hb, w0.y, ocB[1]);
            ocA[2] = fmaf(ha, w0.z, ocA[2]); ocB[2] = fmaf(hb, w0.z, ocB[2]);
            ocA[3] = fmaf(ha, w0.w, ocA[3]); ocB[3] = fmaf(hb, w0.w, ocB[3]);
            ocA[4] = fmaf(ha, w1.x, ocA[4]); ocB[4] = fmaf(hb, w1.x, ocB[4]);
            ocA[5] = fmaf(ha, w1.y, ocA[5]); ocB[5] = fmaf(hb, w1.y, ocB[5]);
            ocA[6] = fmaf(ha, w1.z, ocA[6]); ocB[6] = fmaf(hb, w1.z, ocB[6]);
            ocA[7] = fmaf(ha, w1.w, ocA[7]); ocB[7] = fmaf(hb, w1.w, ocB[7]);
            ocA[8] = fmaf(ha, w2.x, ocA[8]); ocB[8] = fmaf(hb, w2.x, ocB[8]);
            ocA[9] = fmaf(ha, w2.y, ocA[9]); ocB[9] = fmaf(hb, w2.y, ocB[9]);
        }
    }

    {
        float npx = pxA + ocA[0] * DT_F, npy = pyA + ocA[1] * DT_F;
        npx -= floorf(npx * (1.0f / G)) * (float)G;
        npy -= floorf(npy * (1.0f / G)) * (float)G;
        out[aA] = npx; out[NA + aA] = npy;
        out[2 * NA + aA] = ocA[0]; out[3 * NA + aA] = ocA[1];
        float4* dp = (float4*)(g_dpher + (size_t)aA * NC);
        dp[0] = make_float4(ocA[2], ocA[3], ocA[4], ocA[5]);
        dp[1] = make_float4(ocA[6], ocA[7], ocA[8], ocA[9]);
        int pix = (int)rintf(pxA) & GM, piy = (int)rintf(pyA) & GM;
        atomicMax(&g_winner[pix * G + piy], aA + 1);
    }
    {
        float npx = pxB + ocB[0] * DT_F, npy = pyB + ocB[1] * DT_F;
        npx -= floorf(npx * (1.0f / G)) * (float)G;
        npy -= floorf(npy * (1.0f / G)) * (float)G;
        out[aB] = npx; out[NA + aB] = npy;
        out[2 * NA + aB] = ocB[0]; out[3 * NA + aB] = ocB[1];
        float4* dp = (float4*)(g_dpher + (size_t)aB * NC);
        dp[0] = make_float4(ocB[2], ocB[3], ocB[4], ocB[5]);
        dp[1] = make_float4(ocB[6], ocB[7], ocB[8], ocB[9]);
        int pix = (int)rintf(pxB) & GM, piy = (int)rintf(pyB) & GM;
        atomicMax(&g_winner[pix * G + piy], aB + 1);
    }
}

// ---------------------------------------------------------------------------
// Pass 3: dense resolve + decay; 4 cells x 8 channels per thread (float4).
// (R6 verbatim) Resets g_winner so graph replays are identical.
// ---------------------------------------------------------------------------
__global__ void k_update(const float* __restrict__ lat, float* __restrict__ out) {
    int t = blockIdx.x * blockDim.x + threadIdx.x;     // G*G/4 threads
    int4 w4 = ((const int4*)g_winner)[t];
    int wl[4] = {w4.x, w4.y, w4.z, w4.w};
    if (wl[0] | wl[1] | wl[2] | wl[3])
        ((int4*)g_winner)[t] = make_int4(0, 0, 0, 0);

    float dp[4][NC];
#pragma unroll
    for (int u = 0; u < 4; u++) {
        if (wl[u]) {
            const float4* q = (const float4*)(g_dpher + (size_t)(wl[u] - 1) * NC);
            float4 a = q[0], b = q[1];
            dp[u][0] = a.x; dp[u][1] = a.y; dp[u][2] = a.z; dp[u][3] = a.w;
            dp[u][4] = b.x; dp[u][5] = b.y; dp[u][6] = b.z; dp[u][7] = b.w;
        }
    }

    const float4* l4 = (const float4*)lat;
    float4*       o4 = (float4*)(out + 4 * NA);
#pragma unroll
    for (int c = 0; c < NC; c++) {
        float4 v = l4[(size_t)c * (G * G / 4) + t];
        float* vv = (float*)&v;
#pragma unroll
        for (int u = 0; u < 4; u++)
            if (wl[u]) vv[u] = fmaxf(vv[u] + DT_F * dp[u][c], 0.0f);
        v.x *= DEC_F; v.y *= DEC_F; v.z *= DEC_F; v.w *= DEC_F;
        o4[(size_t)c * (G * G / 4) + t] = v;
    }
}

// ---------------------------------------------------------------------------
extern "C" void kernel_launch(void* const* d_in, const int* in_sizes, int n_in,
                              void* d_out, int out_size) {
    const float* pos = (const float*)d_in[0];
    const float* vel = (const float*)d_in[1];
    const float* lat = (const float*)d_in[2];
    const float* W1  = (const float*)d_in[3];
    const float* b1  = (const float*)d_in[4];
    const float* W2  = (const float*)d_in[5];
    const float* b2  = (const float*)d_in[6];
    float* out = (float*)d_out;

    k_box3  <<<(NC * G * G / 4) / 256, 256>>>(lat);
    k_agent <<<NA / 512, 256>>>(pos, vel, W1, b1, W2, b2, out);
    k_update<<<(G * G / 4) / 256, 256>>>(lat, out);
}

// round 15
// speedup vs baseline: 1.3860x; 1.3860x over previous
#include <cuda_runtime.h>
#include <math.h>

#define G     1024
#define GM    (G - 1)
#define NA    262144
#define NC    8
#define DT_F  0.1f
#define DEC_F 0.99f
#define SANG  0.6f
#define SLEN  3.0f

// Scratch (static device globals; no allocation anywhere)
__device__ float g_tmp1[NC * G * G];      // horizontal 3-sum, (C,G,G)       32 MB
__device__ float g_box[G * G * NC];       // 3x3 box sum, transposed (G,G,C) 32 MB
__device__ float g_dpher[NA * NC];        // per-agent pheromone delta        8 MB
__device__ int   g_winner[G * G];         // last-writer agent index + 1     4 MB (zero-init)

__device__ __forceinline__ float tanh_ap(float x) {
    float y; asm("tanh.approx.f32 %0, %1;" : "=f"(y) : "f"(x)); return y;
}

// ---------------------------------------------------------------------------
// Pass 1a: horizontal wrapped 3-sum along y. (R2 verbatim — proven)
// ---------------------------------------------------------------------------
__global__ void k_hsum(const float* __restrict__ lat) {
    int t   = blockIdx.x * blockDim.x + threadIdx.x;   // C*G*G/4 threads
    int y0  = (t & 255) << 2;
    int row = t >> 8;                                  // c*G + x
    const float* r = lat + (size_t)row * G;
    float4 m = *(const float4*)(r + y0);
    float lm = __ldg(r + ((y0 + GM) & GM));
    float rp = __ldg(r + ((y0 + 4) & GM));
    float4 o;
    o.x = lm  + m.x + m.y;
    o.y = m.x + m.y + m.z;
    o.z = m.y + m.z + m.w;
    o.w = m.z + m.w + rp;
    *(float4*)(g_tmp1 + (size_t)row * G + y0) = o;
}

// ---------------------------------------------------------------------------
// Pass 1b: vertical wrapped 3-sum along x + transpose to (x,y,c). (R2 verbatim)
// ---------------------------------------------------------------------------
__global__ void k_vsum() {
    int t  = blockIdx.x * blockDim.x + threadIdx.x;    // G*G threads
    int y  = t & GM;
    int x  = t >> 10;
    int xm = (x + GM) & GM;
    int xp = (x + 1) & GM;
    float o[NC];
#pragma unroll
    for (int c = 0; c < NC; c++) {
        const float* p = g_tmp1 + (size_t)c * (G * G);
        o[c] = p[xm * G + y] + p[x * G + y] + p[xp * G + y];
    }
    float4* dst = (float4*)(g_box + (size_t)t * NC);
    dst[0] = make_float4(o[0], o[1], o[2], o[3]);
    dst[1] = make_float4(o[4], o[5], o[6], o[7]);
}

// ---------------------------------------------------------------------------
// Pass 2: per-agent sense + MLP + outputs. 2 agents per thread, layer-2 fused
// into the layer-1 hidden loop. (R6 verbatim — best measured)
// ---------------------------------------------------------------------------
__device__ __forceinline__ void sense24(float px, float py, float vx, float vy,
                                        float* __restrict__ x) {
    const float CA = 0.8253356149096783f;   // cos(0.6)
    const float SA = 0.5646424733950354f;   // sin(0.6)
    float rinv = rsqrtf(vx * vx + vy * vy);
    float c0 = vx * rinv, s0 = vy * rinv;
    float cd[3], sd[3];
    cd[0] = c0;                 sd[0] = s0;
    cd[1] = c0 * CA - s0 * SA;  sd[1] = s0 * CA + c0 * SA;
    cd[2] = c0 * CA + s0 * SA;  sd[2] = s0 * CA - c0 * SA;
#pragma unroll
    for (int s = 0; s < 3; s++) {
        int ix = ((int)rintf(px + SLEN * cd[s])) & GM;
        int iy = ((int)rintf(py + SLEN * sd[s])) & GM;
        const float4* bp = (const float4*)(g_box + ((size_t)(ix * G + iy)) * NC);
        float4 u = bp[0], v = bp[1];
        x[s * 8 + 0] = u.x; x[s * 8 + 1] = u.y; x[s * 8 + 2] = u.z; x[s * 8 + 3] = u.w;
        x[s * 8 + 4] = v.x; x[s * 8 + 5] = v.y; x[s * 8 + 6] = v.z; x[s * 8 + 7] = v.w;
    }
}

__global__ __launch_bounds__(256) void k_agent(
    const float* __restrict__ pos, const float* __restrict__ vel,
    const float* __restrict__ W1,  const float* __restrict__ b1,
    const float* __restrict__ W2,  const float* __restrict__ b2,
    float* __restrict__ out)
{
    __shared__ __align__(16) float sW1[24 * 64];
    __shared__ __align__(16) float sB1[64];
    __shared__ __align__(16) float sW2[64 * 12];   // rows of 10 padded to 12
    __shared__ __align__(16) float sB2[12];

    int tid = threadIdx.x;
    for (int i = tid; i < 24 * 64; i += 256) sW1[i] = __ldg(W1 + i);
    if (tid < 64) sB1[tid] = __ldg(b1 + tid);
    for (int i = tid; i < 64 * 12; i += 256) {
        int k = i / 12, m = i - k * 12;
        sW2[i] = (m < 10) ? __ldg(W2 + k * 10 + m) : 0.0f;
    }
    if (tid < 12) sB2[tid] = (tid < 10) ? __ldg(b2 + tid) : 0.0f;
    __syncthreads();

    int aA = blockIdx.x * 512 + tid;     // two agents per thread
    int aB = aA + 256;

    float pxA = pos[aA], pyA = pos[NA + aA];
    float vxA = vel[aA], vyA = vel[NA + aA];
    float pxB = pos[aB], pyB = pos[NA + aB];
    float vxB = vel[aB], vyB = vel[NA + aB];

    float xA[24], xB[24];
    sense24(pxA, pyA, vxA, vyA, xA);
    sense24(pxB, pyB, vxB, vyB, xB);

    float ocA[10], ocB[10];
#pragma unroll
    for (int m = 0; m < 10; m++) { ocA[m] = sB2[m]; ocB[m] = sB2[m]; }

#pragma unroll
    for (int jq = 0; jq < 16; jq++) {
        float4 b4 = *(const float4*)&sB1[jq * 4];
        float4 aAcc = b4, bAcc = b4;
#pragma unroll
        for (int k = 0; k < 24; k++) {
            float4 w = *(const float4*)&sW1[k * 64 + jq * 4];
            aAcc.x = fmaf(xA[k], w.x, aAcc.x); aAcc.y = fmaf(xA[k], w.y, aAcc.y);
            aAcc.z = fmaf(xA[k], w.z, aAcc.z); aAcc.w = fmaf(xA[k], w.w, aAcc.w);
            bAcc.x = fmaf(xB[k], w.x, bAcc.x); bAcc.y = fmaf(xB[k], w.y, bAcc.y);
            bAcc.z = fmaf(xB[k], w.z, bAcc.z); bAcc.w = fmaf(xB[k], w.w, bAcc.w);
        }
        float hA[4], hB[4];
        hA[0] = tanh_ap(aAcc.x); hA[1] = tanh_ap(aAcc.y);
        hA[2] = tanh_ap(aAcc.z); hA[3] = tanh_ap(aAcc.w);
        hB[0] = tanh_ap(bAcc.x); hB[1] = tanh_ap(bAcc.y);
        hB[2] = tanh_ap(bAcc.z); hB[3] = tanh_ap(bAcc.w);
#pragma unroll
        for (int u = 0; u < 4; u++) {
            int j = jq * 4 + u;
            const float4* wr = (const float4*)&sW2[j * 12];
            float4 w0 = wr[0], w1 = wr[1], w2 = wr[2];
            float ha = hA[u], hb = hB[u];
            ocA[0] = fmaf(ha, w0.x, ocA[0]); ocB[0] = fmaf(hb, w0.x, ocB[0]);
            ocA[1] = fmaf(ha, w0.y, ocA[1]); ocB[1] = fmaf(hb, w0.y, ocB[1]);
            ocA[2] = fmaf(ha, w0.z, ocA[2]); ocB[2] = fmaf(hb, w0.z, ocB[2]);
            ocA[3] = fmaf(ha, w0.w, ocA[3]); ocB[3] = fmaf(hb, w0.w, ocB[3]);
            ocA[4] = fmaf(ha, w1.x, ocA[4]); ocB[4] = fmaf(hb, w1.x, ocB[4]);
            ocA[5] = fmaf(ha, w1.y, ocA[5]); ocB[5] = fmaf(hb, w1.y, ocB[5]);
            ocA[6] = fmaf(ha, w1.z, ocA[6]); ocB[6] = fmaf(hb, w1.z, ocB[6]);
            ocA[7] = fmaf(ha, w1.w, ocA[7]); ocB[7] = fmaf(hb, w1.w, ocB[7]);
            ocA[8] = fmaf(ha, w2.x, ocA[8]); ocB[8] = fmaf(hb, w2.x, ocB[8]);
            ocA[9] = fmaf(ha, w2.y, ocA[9]); ocB[9] = fmaf(hb, w2.y, ocB[9]);
        }
    }

    {
        float npx = pxA + ocA[0] * DT_F, npy = pyA + ocA[1] * DT_F;
        npx -= floorf(npx * (1.0f / G)) * (float)G;
        npy -= floorf(npy * (1.0f / G)) * (float)G;
        out[aA] = npx; out[NA + aA] = npy;
        out[2 * NA + aA] = ocA[0]; out[3 * NA + aA] = ocA[1];
        float4* dp = (float4*)(g_dpher + (size_t)aA * NC);
        dp[0] = make_float4(ocA[2], ocA[3], ocA[4], ocA[5]);
        dp[1] = make_float4(ocA[6], ocA[7], ocA[8], ocA[9]);
        int pix = (int)rintf(pxA) & GM, piy = (int)rintf(pyA) & GM;
        atomicMax(&g_winner[pix * G + piy], aA + 1);
    }
    {
        float npx = pxB + ocB[0] * DT_F, npy = pyB + ocB[1] * DT_F;
        npx -= floorf(npx * (1.0f / G)) * (float)G;
        npy -= floorf(npy * (1.0f / G)) * (float)G;
        out[aB] = npx; out[NA + aB] = npy;
        out[2 * NA + aB] = ocB[0]; out[3 * NA + aB] = ocB[1];
        float4* dp = (float4*)(g_dpher + (size_t)aB * NC);
        dp[0] = make_float4(ocB[2], ocB[3], ocB[4], ocB[5]);
        dp[1] = make_float4(ocB[6], ocB[7], ocB[8], ocB[9]);
        int pix = (int)rintf(pxB) & GM, piy = (int)rintf(pyB) & GM;
        atomicMax(&g_winner[pix * G + piy], aB + 1);
    }
}

// ---------------------------------------------------------------------------
// Pass 3: dense resolve + decay; NOW 2 cells x 8 channels per thread (float2)
// for higher occupancy / more loads in flight. Resets g_winner for replays.
// ---------------------------------------------------------------------------
__global__ void k_update(const float* __restrict__ lat, float* __restrict__ out) {
    int t = blockIdx.x * blockDim.x + threadIdx.x;     // G*G/2 threads
    int2 w2 = ((const int2*)g_winner)[t];
    int wl0 = w2.x, wl1 = w2.y;
    if (wl0 | wl1)
        ((int2*)g_winner)[t] = make_int2(0, 0);

    float dp0[NC], dp1[NC];
    if (wl0) {
        const float4* q = (const float4*)(g_dpher + (size_t)(wl0 - 1) * NC);
        float4 a = q[0], b = q[1];
        dp0[0] = a.x; dp0[1] = a.y; dp0[2] = a.z; dp0[3] = a.w;
        dp0[4] = b.x; dp0[5] = b.y; dp0[6] = b.z; dp0[7] = b.w;
    }
    if (wl1) {
        const float4* q = (const float4*)(g_dpher + (size_t)(wl1 - 1) * NC);
        float4 a = q[0], b = q[1];
        dp1[0] = a.x; dp1[1] = a.y; dp1[2] = a.z; dp1[3] = a.w;
        dp1[4] = b.x; dp1[5] = b.y; dp1[6] = b.z; dp1[7] = b.w;
    }

    const float2* l2 = (const float2*)lat;
    float2*       o2 = (float2*)(out + 4 * NA);
#pragma unroll
    for (int c = 0; c < NC; c++) {
        float2 v = l2[(size_t)c * (G * G / 2) + t];
        if (wl0) v.x = fmaxf(v.x + DT_F * dp0[c], 0.0f);
        if (wl1) v.y = fmaxf(v.y + DT_F * dp1[c], 0.0f);
        v.x *= DEC_F; v.y *= DEC_F;
        o2[(size_t)c * (G * G / 2) + t] = v;
    }
}

// ---------------------------------------------------------------------------
extern "C" void kernel_launch(void* const* d_in, const int* in_sizes, int n_in,
                              void* d_out, int out_size) {
    const float* pos = (const float*)d_in[0];
    const float* vel = (const float*)d_in[1];
    const float* lat = (const float*)d_in[2];
    const float* W1  = (const float*)d_in[3];
    const float* b1  = (const float*)d_in[4];
    const float* W2  = (const float*)d_in[5];
    const float* b2  = (const float*)d_in[6];
    float* out = (float*)d_out;

    k_hsum  <<<(NC * G * G / 4) / 256, 256>>>(lat);
    k_vsum  <<<(G * G) / 256, 256>>>();
    k_agent <<<NA / 512, 256>>>(pos, vel, W1, b1, W2, b2, out);
    k_update<<<(G * G / 2) / 256, 256>>>(lat, out);
}

// round 17
// speedup vs baseline: 1.4461x; 1.0434x over previous
#include <cuda_runtime.h>
#include <math.h>

#define G     1024
#define GM    (G - 1)
#define NA    262144
#define NC    8
#define DT_F  0.1f
#define DEC_F 0.99f
#define SANG  0.6f
#define SLEN  3.0f

#define AGENT_BLOCKS 512
#define DECAY_BLOCKS 1024

// Scratch (static device globals; no allocation anywhere)
__device__ float g_tmp1[NC * G * G];      // horizontal 3-sum, (C,G,G)       32 MB
__device__ float g_box[G * G * NC];       // 3x3 box sum, transposed (G,G,C) 32 MB
__device__ float g_dpher[NA * NC];        // per-agent pheromone delta        8 MB
__device__ int   g_winner[G * G];         // last-writer agent index + 1     4 MB (zero-init)

__device__ __forceinline__ float tanh_ap(float x) {
    float y; asm("tanh.approx.f32 %0, %1;" : "=f"(y) : "f"(x)); return y;
}

// ---------------------------------------------------------------------------
// Pass 1a: horizontal wrapped 3-sum along y. (R2 verbatim — proven)
// ---------------------------------------------------------------------------
__global__ void k_hsum(const float* __restrict__ lat) {
    int t   = blockIdx.x * blockDim.x + threadIdx.x;   // C*G*G/4 threads
    int y0  = (t & 255) << 2;
    int row = t >> 8;                                  // c*G + x
    const float* r = lat + (size_t)row * G;
    float4 m = *(const float4*)(r + y0);
    float lm = __ldg(r + ((y0 + GM) & GM));
    float rp = __ldg(r + ((y0 + 4) & GM));
    float4 o;
    o.x = lm  + m.x + m.y;
    o.y = m.x + m.y + m.z;
    o.z = m.y + m.z + m.w;
    o.w = m.z + m.w + rp;
    *(float4*)(g_tmp1 + (size_t)row * G + y0) = o;
}

// ---------------------------------------------------------------------------
// Pass 1b: vertical wrapped 3-sum along x + transpose to (x,y,c). (R2 verbatim)
// ---------------------------------------------------------------------------
__global__ void k_vsum() {
    int t  = blockIdx.x * blockDim.x + threadIdx.x;    // G*G threads
    int y  = t & GM;
    int x  = t >> 10;
    int xm = (x + GM) & GM;
    int xp = (x + 1) & GM;
    float o[NC];
#pragma unroll
    for (int c = 0; c < NC; c++) {
        const float* p = g_tmp1 + (size_t)c * (G * G);
        o[c] = p[xm * G + y] + p[x * G + y] + p[xp * G + y];
    }
    float4* dst = (float4*)(g_box + (size_t)t * NC);
    dst[0] = make_float4(o[0], o[1], o[2], o[3]);
    dst[1] = make_float4(o[4], o[5], o[6], o[7]);
}

// ---------------------------------------------------------------------------
// Pass 2 (co-scheduled): blocks [0,AGENT_BLOCKS) = agent MLP (R6 verbatim);
// blocks [AGENT_BLOCKS,+DECAY_BLOCKS) = decay stream out=lat*DECAY.
// The decay blocks fill agent wave-quantization bubbles (R12: combined
// 37.6us vs 50+11 separate). k_update later overwrites out fully, so the
// decay writes are harmless filler that also warms L2 with lat.
// ---------------------------------------------------------------------------
__device__ __forceinline__ void sense24(float px, float py, float vx, float vy,
                                        float* __restrict__ x) {
    const float CA = 0.8253356149096783f;   // cos(0.6)
    const float SA = 0.5646424733950354f;   // sin(0.6)
    float rinv = rsqrtf(vx * vx + vy * vy);
    float c0 = vx * rinv, s0 = vy * rinv;
    float cd[3], sd[3];
    cd[0] = c0;                 sd[0] = s0;
    cd[1] = c0 * CA - s0 * SA;  sd[1] = s0 * CA + c0 * SA;
    cd[2] = c0 * CA + s0 * SA;  sd[2] = s0 * CA - c0 * SA;
#pragma unroll
    for (int s = 0; s < 3; s++) {
        int ix = ((int)rintf(px + SLEN * cd[s])) & GM;
        int iy = ((int)rintf(py + SLEN * sd[s])) & GM;
        const float4* bp = (const float4*)(g_box + ((size_t)(ix * G + iy)) * NC);
        float4 u = bp[0], v = bp[1];
        x[s * 8 + 0] = u.x; x[s * 8 + 1] = u.y; x[s * 8 + 2] = u.z; x[s * 8 + 3] = u.w;
        x[s * 8 + 4] = v.x; x[s * 8 + 5] = v.y; x[s * 8 + 6] = v.z; x[s * 8 + 7] = v.w;
    }
}

__global__ __launch_bounds__(256) void k_agent_decay(
    const float* __restrict__ pos, const float* __restrict__ vel,
    const float* __restrict__ lat,
    const float* __restrict__ W1,  const float* __restrict__ b1,
    const float* __restrict__ W2,  const float* __restrict__ b2,
    float* __restrict__ out)
{
    int tid = threadIdx.x;

    // ---------------- decay blocks: pure streaming filler ----------------
    if (blockIdx.x >= AGENT_BLOCKS) {
        int b = blockIdx.x - AGENT_BLOCKS;
        const float4* l4 = (const float4*)lat;
        float4*       o4 = (float4*)(out + 4 * NA);
        const int total = NC * G * G / 4;              // 2M float4
#pragma unroll 4
        for (int i = b * 256 + tid; i < total; i += DECAY_BLOCKS * 256) {
            float4 v = __ldg(l4 + i);
            v.x *= DEC_F; v.y *= DEC_F; v.z *= DEC_F; v.w *= DEC_F;
            o4[i] = v;
        }
        return;
    }

    // ---------------- agent blocks: R6-verbatim MLP ----------------
    __shared__ __align__(16) float sW1[24 * 64];
    __shared__ __align__(16) float sB1[64];
    __shared__ __align__(16) float sW2[64 * 12];   // rows of 10 padded to 12
    __shared__ __align__(16) float sB2[12];

    for (int i = tid; i < 24 * 64; i += 256) sW1[i] = __ldg(W1 + i);
    if (tid < 64) sB1[tid] = __ldg(b1 + tid);
    for (int i = tid; i < 64 * 12; i += 256) {
        int k = i / 12, m = i - k * 12;
        sW2[i] = (m < 10) ? __ldg(W2 + k * 10 + m) : 0.0f;
    }
    if (tid < 12) sB2[tid] = (tid < 10) ? __ldg(b2 + tid) : 0.0f;
    __syncthreads();

    int aA = blockIdx.x * 512 + tid;     // two agents per thread
    int aB = aA + 256;

    float pxA = pos[aA], pyA = pos[NA + aA];
    float vxA = vel[aA], vyA = vel[NA + aA];
    float pxB = pos[aB], pyB = pos[NA + aB];
    float vxB = vel[aB], vyB = vel[NA + aB];

    float xA[24], xB[24];
    sense24(pxA, pyA, vxA, vyA, xA);
    sense24(pxB, pyB, vxB, vyB, xB);

    float ocA[10], ocB[10];
#pragma unroll
    for (int m = 0; m < 10; m++) { ocA[m] = sB2[m]; ocB[m] = sB2[m]; }

#pragma unroll
    for (int jq = 0; jq < 16; jq++) {
        float4 b4 = *(const float4*)&sB1[jq * 4];
        float4 aAcc = b4, bAcc = b4;
#pragma unroll
        for (int k = 0; k < 24; k++) {
            float4 w = *(const float4*)&sW1[k * 64 + jq * 4];
            aAcc.x = fmaf(xA[k], w.x, aAcc.x); aAcc.y = fmaf(xA[k], w.y, aAcc.y);
            aAcc.z = fmaf(xA[k], w.z, aAcc.z); aAcc.w = fmaf(xA[k], w.w, aAcc.w);
            bAcc.x = fmaf(xB[k], w.x, bAcc.x); bAcc.y = fmaf(xB[k], w.y, bAcc.y);
            bAcc.z = fmaf(xB[k], w.z, bAcc.z); bAcc.w = fmaf(xB[k], w.w, bAcc.w);
        }
        float hA[4], hB[4];
        hA[0] = tanh_ap(aAcc.x); hA[1] = tanh_ap(aAcc.y);
        hA[2] = tanh_ap(aAcc.z); hA[3] = tanh_ap(aAcc.w);
        hB[0] = tanh_ap(bAcc.x); hB[1] = tanh_ap(bAcc.y);
        hB[2] = tanh_ap(bAcc.z); hB[3] = tanh_ap(bAcc.w);
#pragma unroll
        for (int u = 0; u < 4; u++) {
            int j = jq * 4 + u;
            const float4* wr = (const float4*)&sW2[j * 12];
            float4 w0 = wr[0], w1 = wr[1], w2 = wr[2];
            float ha = hA[u], hb = hB[u];
            ocA[0] = fmaf(ha, w0.x, ocA[0]); ocB[0] = fmaf(hb, w0.x, ocB[0]);
            ocA[1] = fmaf(ha, w0.y, ocA[1]); ocB[1] = fmaf(hb, w0.y, ocB[1]);
            ocA[2] = fmaf(ha, w0.z, ocA[2]); ocB[2] = fmaf(hb, w0.z, ocB[2]);
            ocA[3] = fmaf(ha, w0.w, ocA[3]); ocB[3] = fmaf(hb, w0.w, ocB[3]);
            ocA[4] = fmaf(ha, w1.x, ocA[4]); ocB[4] = fmaf(hb, w1.x, ocB[4]);
            ocA[5] = fmaf(ha, w1.y, ocA[5]); ocB[5] = fmaf(hb, w1.y, ocB[5]);
            ocA[6] = fmaf(ha, w1.z, ocA[6]); ocB[6] = fmaf(hb, w1.z, ocB[6]);
            ocA[7] = fmaf(ha, w1.w, ocA[7]); ocB[7] = fmaf(hb, w1.w, ocB[7]);
            ocA[8] = fmaf(ha, w2.x, ocA[8]); ocB[8] = fmaf(hb, w2.x, ocB[8]);
            ocA[9] = fmaf(ha, w2.y, ocA[9]); ocB[9] = fmaf(hb, w2.y, ocB[9]);
        }
    }

    {
        float npx = pxA + ocA[0] * DT_F, npy = pyA + ocA[1] * DT_F;
        npx -= floorf(npx * (1.0f / G)) * (float)G;
        npy -= floorf(npy * (1.0f / G)) * (float)G;
        out[aA] = npx; out[NA + aA] = npy;
        out[2 * NA + aA] = ocA[0]; out[3 * NA + aA] = ocA[1];
        float4* dp = (float4*)(g_dpher + (size_t)aA * NC);
        dp[0] = make_float4(ocA[2], ocA[3], ocA[4], ocA[5]);
        dp[1] = make_float4(ocA[6], ocA[7], ocA[8], ocA[9]);
        int pix = (int)rintf(pxA) & GM, piy = (int)rintf(pyA) & GM;
        atomicMax(&g_winner[pix * G + piy], aA + 1);
    }
    {
        float npx = pxB + ocB[0] * DT_F, npy = pyB + ocB[1] * DT_F;
        npx -= floorf(npx * (1.0f / G)) * (float)G;
        npy -= floorf(npy * (1.0f / G)) * (float)G;
        out[aB] = npx; out[NA + aB] = npy;
        out[2 * NA + aB] = ocB[0]; out[3 * NA + aB] = ocB[1];
        float4* dp = (float4*)(g_dpher + (size_t)aB * NC);
        dp[0] = make_float4(ocB[2], ocB[3], ocB[4], ocB[5]);
        dp[1] = make_float4(ocB[6], ocB[7], ocB[8], ocB[9]);
        int pix = (int)rintf(pxB) & GM, piy = (int)rintf(pyB) & GM;
        atomicMax(&g_winner[pix * G + piy], aB + 1);
    }
}

// ---------------------------------------------------------------------------
// Pass 3: dense resolve + decay; 4 cells x 8 channels per thread (float4).
// (R6 verbatim — best measured.) Overwrites everything the decay-filler
// wrote, applying winner fix-ups. Resets g_winner so replays are identical.
// ---------------------------------------------------------------------------
__global__ void k_update(const float* __restrict__ lat, float* __restrict__ out) {
    int t = blockIdx.x * blockDim.x + threadIdx.x;     // G*G/4 threads
    int4 w4 = ((const int4*)g_winner)[t];
    int wl[4] = {w4.x, w4.y, w4.z, w4.w};
    if (wl[0] | wl[1] | wl[2] | wl[3])
        ((int4*)g_winner)[t] = make_int4(0, 0, 0, 0);

    float dp[4][NC];
#pragma unroll
    for (int u = 0; u < 4; u++) {
        if (wl[u]) {
            const float4* q = (const float4*)(g_dpher + (size_t)(wl[u] - 1) * NC);
            float4 a = q[0], b = q[1];
            dp[u][0] = a.x; dp[u][1] = a.y; dp[u][2] = a.z; dp[u][3] = a.w;
            dp[u][4] = b.x; dp[u][5] = b.y; dp[u][6] = b.z; dp[u][7] = b.w;
        }
    }

    const float4* l4 = (const float4*)lat;
    float4*       o4 = (float4*)(out + 4 * NA);
#pragma unroll
    for (int c = 0; c < NC; c++) {
        float4 v = l4[(size_t)c * (G * G / 4) + t];
        float* vv = (float*)&v;
#pragma unroll
        for (int u = 0; u < 4; u++)
            if (wl[u]) vv[u] = fmaxf(vv[u] + DT_F * dp[u][c], 0.0f);
        v.x *= DEC_F; v.y *= DEC_F; v.z *= DEC_F; v.w *= DEC_F;
        o4[(size_t)c * (G * G / 4) + t] = v;
    }
}

// ---------------------------------------------------------------------------
extern "C" void kernel_launch(void* const* d_in, const int* in_sizes, int n_in,
                              void* d_out, int out_size) {
    const float* pos = (const float*)d_in[0];
    const float* vel = (const float*)d_in[1];
    const float* lat = (const float*)d_in[2];
    const float* W1  = (const float*)d_in[3];
    const float* b1  = (const float*)d_in[4];
    const float* W2  = (const float*)d_in[5];
    const float* b2  = (const float*)d_in[6];
    float* out = (float*)d_out;

    k_hsum       <<<(NC * G * G / 4) / 256, 256>>>(lat);
    k_vsum       <<<(G * G) / 256, 256>>>();
    k_agent_decay<<<AGENT_BLOCKS + DECAY_BLOCKS, 256>>>(pos, vel, lat, W1, b1, W2, b2, out);
    k_update     <<<(G * G / 4) / 256, 256>>>(lat, out);
}